// round 5
// baseline (speedup 1.0000x reference)
#include <cuda_runtime.h>

#define BATCH 16
#define CIN   768
#define L0    4096
#define L1    2048
#define L2    1024

__device__ float g_h1[BATCH * 32 * L1];
__device__ float g_A[BATCH * 64 * L2];
__device__ float g_B[BATCH * 64 * L2];
__device__ float g_C[BATCH * 64 * L2];
__device__ float g_d1[BATCH * 32 * L1];
__device__ float g_e2[512];

// ---- conv1: x(16,768,4096)->h1(16,32,2048), k4 s2 p1, ReLU -----------------
__global__ __launch_bounds__(256) void conv1_k(const float* __restrict__ x,
                                               const float* __restrict__ w,
                                               const float* __restrict__ bias) {
    extern __shared__ float sm[];
    float* xs = sm;               // [32][260]
    float* ws = sm + 32 * 260;    // [32*4][36]
    const int b = blockIdx.y, t0 = blockIdx.x * 128;
    const int tid = threadIdx.x, lane = tid & 31, og = tid >> 5;
    float acc[4][4];
#pragma unroll
    for (int i = 0; i < 4; i++)
#pragma unroll
        for (int j = 0; j < 4; j++) acc[i][j] = 0.f;

    for (int c0 = 0; c0 < CIN; c0 += 32) {
        for (int i = tid; i < 32 * 4 * 32; i += 256) {
            int k = i & 3, c = (i >> 2) & 31, o = i >> 7;
            ws[(c * 4 + k) * 36 + o] = w[((o * CIN) + c0 + c) * 4 + k];
        }
        for (int i = tid; i < 32 * 258; i += 256) {
            int c = i / 258, p = i - c * 258;
            int gp = 2 * t0 - 1 + p;
            xs[c * 260 + p] = (gp >= 0 && gp < L0) ? x[((b * CIN) + c0 + c) * L0 + gp] : 0.f;
        }
        __syncthreads();
#pragma unroll 4
        for (int c = 0; c < 32; ++c) {
            float4 w0 = *(const float4*)&ws[(c * 4 + 0) * 36 + og * 4];
            float4 w1 = *(const float4*)&ws[(c * 4 + 1) * 36 + og * 4];
            float4 w2 = *(const float4*)&ws[(c * 4 + 2) * 36 + og * 4];
            float4 w3 = *(const float4*)&ws[(c * 4 + 3) * 36 + og * 4];
#pragma unroll
            for (int tj = 0; tj < 4; tj++) {
                const float* xr = &xs[c * 260 + 2 * (lane + 32 * tj)];
                float x0 = xr[0], x1 = xr[1], x2 = xr[2], x3 = xr[3];
                acc[0][tj] += w0.x * x0 + w1.x * x1 + w2.x * x2 + w3.x * x3;
                acc[1][tj] += w0.y * x0 + w1.y * x1 + w2.y * x2 + w3.y * x3;
                acc[2][tj] += w0.z * x0 + w1.z * x1 + w2.z * x2 + w3.z * x3;
                acc[3][tj] += w0.w * x0 + w1.w * x1 + w2.w * x2 + w3.w * x3;
            }
        }
        __syncthreads();
    }
#pragma unroll
    for (int oi = 0; oi < 4; oi++) {
        int o = og * 4 + oi;
        float bv = bias[o];
#pragma unroll
        for (int tj = 0; tj < 4; tj++)
            g_h1[((b * 32) + o) * L1 + t0 + lane + 32 * tj] = fmaxf(acc[oi][tj] + bv, 0.f);
    }
}

// ---- conv2: h1->A(16,64,1024), k4 s2 p1, ReLU ------------------------------
__global__ __launch_bounds__(256) void conv2_k(const float* __restrict__ w,
                                               const float* __restrict__ bias,
                                               float* __restrict__ out) {
    extern __shared__ float sm[];
    float* xs = sm;               // [32][132]
    float* ws = sm + 32 * 132;    // [32*4][68]
    const int b = blockIdx.y, t0 = blockIdx.x * 64;
    const int tid = threadIdx.x, lane = tid & 31, og = tid >> 5;
    float acc[8][2];
#pragma unroll
    for (int i = 0; i < 8; i++) { acc[i][0] = 0.f; acc[i][1] = 0.f; }

    for (int i = tid; i < 64 * 32 * 4; i += 256) {
        int k = i & 3, c = (i >> 2) & 31, o = i >> 7;
        ws[(c * 4 + k) * 68 + o] = w[((o * 32) + c) * 4 + k];
    }
    for (int i = tid; i < 32 * 130; i += 256) {
        int c = i / 130, p = i - c * 130;
        int gp = 2 * t0 - 1 + p;
        xs[c * 132 + p] = (gp >= 0 && gp < L1) ? g_h1[((b * 32) + c) * L1 + gp] : 0.f;
    }
    __syncthreads();
#pragma unroll 4
    for (int c = 0; c < 32; ++c) {
        float wr[4][8];
#pragma unroll
        for (int k = 0; k < 4; k++) {
            float4 a  = *(const float4*)&ws[(c * 4 + k) * 68 + og * 8];
            float4 b4 = *(const float4*)&ws[(c * 4 + k) * 68 + og * 8 + 4];
            wr[k][0] = a.x;  wr[k][1] = a.y;  wr[k][2] = a.z;  wr[k][3] = a.w;
            wr[k][4] = b4.x; wr[k][5] = b4.y; wr[k][6] = b4.z; wr[k][7] = b4.w;
        }
#pragma unroll
        for (int tj = 0; tj < 2; tj++) {
            const float* xr = &xs[c * 132 + 2 * (lane + 32 * tj)];
            float x0 = xr[0], x1 = xr[1], x2 = xr[2], x3 = xr[3];
#pragma unroll
            for (int oi = 0; oi < 8; oi++)
                acc[oi][tj] += wr[0][oi] * x0 + wr[1][oi] * x1 + wr[2][oi] * x2 + wr[3][oi] * x3;
        }
    }
#pragma unroll
    for (int oi = 0; oi < 8; oi++) {
        int o = og * 8 + oi;
        float bv = bias[o];
#pragma unroll
        for (int tj = 0; tj < 2; tj++)
            out[((b * 64) + o) * L2 + t0 + lane + 32 * tj] = fmaxf(acc[oi][tj] + bv, 0.f);
    }
}

// ---- generic conv, stride1, pad K/2, T=1024 --------------------------------
template <int Ci, int Co, int K>
__global__ __launch_bounds__(256) void gconv_k(const float* __restrict__ in,
                                               float* __restrict__ out,
                                               const float* __restrict__ res,
                                               const float* __restrict__ w,
                                               const float* __restrict__ bias,
                                               int relu_in, int relu_out) {
    extern __shared__ float sm[];
    constexpr int CoP = Co + 4;
    constexpr int OPT = Co / 8;
    constexpr int H = K / 2, W = 64 + 2 * H;
    float* xs = sm;               // [Ci][68]
    float* ws = sm + Ci * 68;     // [Ci*K][CoP]
    const int b = blockIdx.y, t0 = blockIdx.x * 64;
    const int tid = threadIdx.x, lane = tid & 31, og = tid >> 5;
    float acc[OPT][2];
#pragma unroll
    for (int i = 0; i < OPT; i++) { acc[i][0] = 0.f; acc[i][1] = 0.f; }

    for (int i = tid; i < Ci * Co * K; i += 256) {
        int k = i % K, r = i / K, c = r % Ci, o = r / Ci;
        ws[(c * K + k) * CoP + o] = w[(o * Ci + c) * K + k];
    }
    for (int i = tid; i < Ci * W; i += 256) {
        int c = i / W, p = i - c * W;
        int gp = t0 - H + p;
        float v = (gp >= 0 && gp < L2) ? in[((b * Ci) + c) * L2 + gp] : 0.f;
        if (relu_in) v = fmaxf(v, 0.f);
        xs[c * 68 + p] = v;
    }
    __syncthreads();
#pragma unroll 2
    for (int c = 0; c < Ci; ++c) {
        float wr[K][OPT];
#pragma unroll
        for (int k = 0; k < K; k++)
#pragma unroll
            for (int oi = 0; oi < OPT; oi++)
                wr[k][oi] = ws[(c * K + k) * CoP + og * OPT + oi];
#pragma unroll
        for (int tj = 0; tj < 2; tj++) {
            const float* xr = &xs[c * 68 + lane + 32 * tj];
#pragma unroll
            for (int oi = 0; oi < OPT; oi++) {
                float s = 0.f;
#pragma unroll
                for (int k = 0; k < K; k++) s += wr[k][oi] * xr[k];
                acc[oi][tj] += s;
            }
        }
    }
#pragma unroll
    for (int oi = 0; oi < OPT; oi++) {
        int o = og * OPT + oi;
        float bv = bias ? bias[o] : 0.f;
#pragma unroll
        for (int tj = 0; tj < 2; tj++) {
            int t = t0 + lane + 32 * tj;
            float v = acc[oi][tj] + bv;
            if (res) v += res[((b * Co) + o) * L2 + t];
            if (relu_out) v = fmaxf(v, 0.f);
            out[((b * Co) + o) * L2 + t] = v;
        }
    }
}

// ---- codebook squared norms ------------------------------------------------
__global__ void e2_k(const float* __restrict__ emb) {
    int c = blockIdx.x * blockDim.x + threadIdx.x;
    if (c < 512) {
        float s = 0.f;
#pragma unroll 8
        for (int d = 0; d < 64; ++d) { float v = emb[c * 64 + d]; s += v * v; }
        g_e2[c] = s;
    }
}

// ---- VQ: nearest codebook row per (b,t) ------------------------------------
__global__ __launch_bounds__(256) void vq_k(const float* __restrict__ z,
                                            float* __restrict__ q,
                                            const float* __restrict__ emb) {
    extern __shared__ float sm[];
    float* zs  = sm;              // [64][33]
    float* es  = zs + 64 * 33;    // [512][17]
    float* e2s = es + 512 * 17;   // [512]
    __shared__ int idxs[32];
    const int v0 = blockIdx.x * 32;
    const int b = v0 >> 10, t0 = v0 & 1023;
    const int tid = threadIdx.x, lane = tid & 31, vg = tid >> 5;

    for (int i = tid; i < 64 * 32; i += 256) {
        int d = i >> 5, vv = i & 31;
        zs[d * 33 + vv] = z[((b * 64) + d) * L2 + t0 + vv];
    }
    for (int i = tid; i < 512; i += 256) e2s[i] = g_e2[i];

    float acc[4][16];
#pragma unroll
    for (int i = 0; i < 4; i++)
#pragma unroll
        for (int j = 0; j < 16; j++) acc[i][j] = 0.f;

    for (int k0 = 0; k0 < 64; k0 += 16) {
        __syncthreads();
        for (int i = tid; i < 512 * 4; i += 256) {
            int c = i >> 2, kq = i & 3;
            float4 v = *(const float4*)&emb[c * 64 + k0 + kq * 4];
            float* d = &es[c * 17 + kq * 4];
            d[0] = v.x; d[1] = v.y; d[2] = v.z; d[3] = v.w;
        }
        __syncthreads();
#pragma unroll
        for (int kd = 0; kd < 16; ++kd) {
            float zv0 = zs[(k0 + kd) * 33 + vg * 4 + 0];
            float zv1 = zs[(k0 + kd) * 33 + vg * 4 + 1];
            float zv2 = zs[(k0 + kd) * 33 + vg * 4 + 2];
            float zv3 = zs[(k0 + kd) * 33 + vg * 4 + 3];
#pragma unroll
            for (int cc = 0; cc < 16; ++cc) {
                float ev = es[(lane + 32 * cc) * 17 + kd];
                acc[0][cc] += zv0 * ev;
                acc[1][cc] += zv1 * ev;
                acc[2][cc] += zv2 * ev;
                acc[3][cc] += zv3 * ev;
            }
        }
    }
#pragma unroll
    for (int vv = 0; vv < 4; ++vv) {
        float mv = 3.0e38f; int mi = 0;
#pragma unroll
        for (int cc = 0; cc < 16; ++cc) {
            int c = lane + 32 * cc;
            float val = e2s[c] - 2.0f * acc[vv][cc];
            if (val < mv) { mv = val; mi = c; }
        }
        for (int off = 16; off > 0; off >>= 1) {
            float ov = __shfl_down_sync(0xffffffffu, mv, off);
            int   oi = __shfl_down_sync(0xffffffffu, mi, off);
            if (ov < mv || (ov == mv && oi < mi)) { mv = ov; mi = oi; }
        }
        if (lane == 0) idxs[vg * 4 + vv] = mi;
    }
    __syncthreads();
    for (int i = tid; i < 64 * 32; i += 256) {
        int d = i >> 5, vv = i & 31;
        q[((b * 64) + d) * L2 + t0 + vv] = emb[idxs[vv] * 64 + d];
    }
}

// ---- dect1: ConvTranspose1d 64->32, k4 s2 p1, bias, ReLU -------------------
__global__ __launch_bounds__(256) void dect1_k(const float* __restrict__ in,
                                               const float* __restrict__ w,
                                               const float* __restrict__ bias) {
    extern __shared__ float sm[];
    float* xs = sm;               // [64][68]
    float* ws = sm + 64 * 68;     // [64*4][36]
    const int b = blockIdx.y, t0 = blockIdx.x * 128;
    const int tid = threadIdx.x, lane = tid & 31, og = tid >> 5;
    const int s0 = t0 / 2 - 1;
    float acc[4][4];
#pragma unroll
    for (int i = 0; i < 4; i++)
#pragma unroll
        for (int j = 0; j < 4; j++) acc[i][j] = 0.f;

    for (int i = tid; i < 64 * 32 * 4; i += 256) {
        int k = i & 3, o = (i >> 2) & 31, c = i >> 7;
        ws[(c * 4 + k) * 36 + o] = w[((c * 32) + o) * 4 + k];
    }
    for (int i = tid; i < 64 * 66; i += 256) {
        int c = i / 66, ls = i - c * 66;
        int s = s0 + ls;
        xs[c * 68 + ls] = (s >= 0 && s < L2) ? in[((b * 64) + c) * L2 + s] : 0.f;
    }
    __syncthreads();
    const int khi = (lane & 1) ? 0 : 1;
    const int klo = khi + 2;
    const int lsb = ((lane + (lane & 1)) >> 1) + 1;
#pragma unroll 2
    for (int c = 0; c < 64; ++c) {
        float4 wh = *(const float4*)&ws[(c * 4 + khi) * 36 + og * 4];
        float4 wl = *(const float4*)&ws[(c * 4 + klo) * 36 + og * 4];
#pragma unroll
        for (int tj = 0; tj < 4; tj++) {
            int lh = lsb + 16 * tj;
            float xh = xs[c * 68 + lh], xl = xs[c * 68 + lh - 1];
            acc[0][tj] += wh.x * xh + wl.x * xl;
            acc[1][tj] += wh.y * xh + wl.y * xl;
            acc[2][tj] += wh.z * xh + wl.z * xl;
            acc[3][tj] += wh.w * xh + wl.w * xl;
        }
    }
#pragma unroll
    for (int oi = 0; oi < 4; oi++) {
        int o = og * 4 + oi;
        float bv = bias[o];
#pragma unroll
        for (int tj = 0; tj < 4; tj++)
            g_d1[((b * 32) + o) * L1 + t0 + lane + 32 * tj] = fmaxf(acc[oi][tj] + bv, 0.f);
    }
}

// ---- dect2: ConvTranspose1d 32->64, k4 s2 p1, bias -> d_out ----------------
__global__ __launch_bounds__(256) void dect2_k(const float* __restrict__ w,
                                               const float* __restrict__ bias,
                                               float* __restrict__ out) {
    extern __shared__ float sm[];
    float* xs = sm;               // [32][68]
    float* ws = sm + 32 * 68;     // [32*4][68]
    const int b = blockIdx.y, t0 = blockIdx.x * 128;
    const int tid = threadIdx.x, lane = tid & 31, og = tid >> 5;
    const int s0 = t0 / 2 - 1;
    float acc[8][4];
#pragma unroll
    for (int i = 0; i < 8; i++)
#pragma unroll
        for (int j = 0; j < 4; j++) acc[i][j] = 0.f;

    for (int i = tid; i < 32 * 64 * 4; i += 256) {
        int k = i & 3, o = (i >> 2) & 63, c = i >> 8;
        ws[(c * 4 + k) * 68 + o] = w[((c * 64) + o) * 4 + k];
    }
    for (int i = tid; i < 32 * 66; i += 256) {
        int c = i / 66, ls = i - c * 66;
        int s = s0 + ls;
        xs[c * 68 + ls] = (s >= 0 && s < L1) ? g_d1[((b * 32) + c) * L1 + s] : 0.f;
    }
    __syncthreads();
    const int khi = (lane & 1) ? 0 : 1;
    const int klo = khi + 2;
    const int lsb = ((lane + (lane & 1)) >> 1) + 1;
#pragma unroll 2
    for (int c = 0; c < 32; ++c) {
        float4 wh0 = *(const float4*)&ws[(c * 4 + khi) * 68 + og * 8];
        float4 wh1 = *(const float4*)&ws[(c * 4 + khi) * 68 + og * 8 + 4];
        float4 wl0 = *(const float4*)&ws[(c * 4 + klo) * 68 + og * 8];
        float4 wl1 = *(const float4*)&ws[(c * 4 + klo) * 68 + og * 8 + 4];
        float wh[8] = {wh0.x, wh0.y, wh0.z, wh0.w, wh1.x, wh1.y, wh1.z, wh1.w};
        float wl[8] = {wl0.x, wl0.y, wl0.z, wl0.w, wl1.x, wl1.y, wl1.z, wl1.w};
#pragma unroll
        for (int tj = 0; tj < 4; tj++) {
            int lh = lsb + 16 * tj;
            float xh = xs[c * 68 + lh], xl = xs[c * 68 + lh - 1];
#pragma unroll
            for (int oi = 0; oi < 8; oi++)
                acc[oi][tj] += wh[oi] * xh + wl[oi] * xl;
        }
    }
#pragma unroll
    for (int oi = 0; oi < 8; oi++) {
        int o = og * 8 + oi;
        float bv = bias[o];
#pragma unroll
        for (int tj = 0; tj < 4; tj++)
            out[((b * 64) + o) * L0 + t0 + lane + 32 * tj] = acc[oi][tj] + bv;
    }
}

extern "C" void kernel_launch(void* const* d_in, const int* in_sizes, int n_in,
                              void* d_out, int out_size) {
    const float* x        = (const float*)d_in[0];
    const float* enc_w1   = (const float*)d_in[1];
    const float* enc_b1   = (const float*)d_in[2];
    const float* enc_w2   = (const float*)d_in[3];
    const float* enc_b2   = (const float*)d_in[4];
    const float* enc_w3   = (const float*)d_in[5];
    const float* enc_b3   = (const float*)d_in[6];
    const float* enc_r0_w1 = (const float*)d_in[7];
    const float* enc_r0_w2 = (const float*)d_in[8];
    const float* enc_r1_w1 = (const float*)d_in[9];
    const float* enc_r1_w2 = (const float*)d_in[10];
    const float* prevq_w  = (const float*)d_in[11];
    const float* prevq_b  = (const float*)d_in[12];
    const float* emb      = (const float*)d_in[13];
    const float* dec_w1   = (const float*)d_in[14];
    const float* dec_b1   = (const float*)d_in[15];
    const float* dec_r0_w1 = (const float*)d_in[16];
    const float* dec_r0_w2 = (const float*)d_in[17];
    const float* dec_r1_w1 = (const float*)d_in[18];
    const float* dec_r1_w2 = (const float*)d_in[19];
    const float* dect1_w  = (const float*)d_in[20];
    const float* dect1_b  = (const float*)d_in[21];
    const float* dect2_w  = (const float*)d_in[22];
    const float* dect2_b  = (const float*)d_in[23];
    float* out = (float*)d_out;

    float *A, *B, *C;
    cudaGetSymbolAddress((void**)&A, g_A);
    cudaGetSymbolAddress((void**)&B, g_B);
    cudaGetSymbolAddress((void**)&C, g_C);

    cudaFuncSetAttribute(conv1_k, cudaFuncAttributeMaxDynamicSharedMemorySize, 65536);
    cudaFuncSetAttribute(conv2_k, cudaFuncAttributeMaxDynamicSharedMemorySize, 65536);
    cudaFuncSetAttribute(gconv_k<64, 64, 3>, cudaFuncAttributeMaxDynamicSharedMemorySize, 98304);
    cudaFuncSetAttribute(dect1_k, cudaFuncAttributeMaxDynamicSharedMemorySize, 65536);

    dim3 blk(256);
    // encoder
    conv1_k<<<dim3(L1 / 128, BATCH), blk, (32 * 260 + 128 * 36) * 4>>>(x, enc_w1, enc_b1);
    conv2_k<<<dim3(L2 / 64, BATCH), blk, (32 * 132 + 128 * 68) * 4>>>(enc_w2, enc_b2, A);
    size_t sm_643 = (64 * 68 + 64 * 3 * 68) * 4;
    size_t sm_323 = (64 * 68 + 64 * 3 * 36) * 4;
    size_t sm_641 = (32 * 68 + 32 * 68) * 4;
    size_t sm_6411 = (64 * 68 + 64 * 68) * 4;
    dim3 gg(L2 / 64, BATCH);
    gconv_k<64, 64, 3><<<gg, blk, sm_643>>>(A, B, nullptr, enc_w3, enc_b3, 0, 0);
    gconv_k<64, 32, 3><<<gg, blk, sm_323>>>(B, C, nullptr, enc_r0_w1, nullptr, 1, 1);
    gconv_k<32, 64, 1><<<gg, blk, sm_641>>>(C, A, B, enc_r0_w2, nullptr, 0, 0);
    gconv_k<64, 32, 3><<<gg, blk, sm_323>>>(A, C, nullptr, enc_r1_w1, nullptr, 1, 1);
    gconv_k<32, 64, 1><<<gg, blk, sm_641>>>(C, B, A, enc_r1_w2, nullptr, 0, 1);
    gconv_k<64, 64, 1><<<gg, blk, sm_6411>>>(B, A, nullptr, prevq_w, prevq_b, 0, 0);
    // VQ
    e2_k<<<2, 256>>>(emb);
    vq_k<<<BATCH * L2 / 32, blk, (64 * 33 + 512 * 17 + 512) * 4>>>(A, C, emb);
    // decoder
    gconv_k<64, 64, 3><<<gg, blk, sm_643>>>(C, A, nullptr, dec_w1, dec_b1, 0, 0);
    gconv_k<64, 32, 3><<<gg, blk, sm_323>>>(A, B, nullptr, dec_r0_w1, nullptr, 1, 1);
    gconv_k<32, 64, 1><<<gg, blk, sm_641>>>(B, C, A, dec_r0_w2, nullptr, 0, 0);
    gconv_k<64, 32, 3><<<gg, blk, sm_323>>>(C, B, nullptr, dec_r1_w1, nullptr, 1, 1);
    gconv_k<32, 64, 1><<<gg, blk, sm_641>>>(B, A, C, dec_r1_w2, nullptr, 0, 1);
    dect1_k<<<dim3(L1 / 128, BATCH), blk, (64 * 68 + 256 * 36) * 4>>>(A, dect1_w, dect1_b);
    dect2_k<<<dim3(L0 / 128, BATCH), blk, (32 * 68 + 128 * 68) * 4>>>(dect2_w, dect2_b, out);
}